// round 2
// baseline (speedup 1.0000x reference)
#include <cuda_runtime.h>
#include <math.h>

// Problem constants (shapes fixed by the dataset; n_rows derived at runtime).
#define FDIM 64
#define HID  128
#define BM   128
#define BK   8

#define MAX_ATOMS 100000

// Scratch (static __device__ — no allocation allowed in kernel_launch).
__device__ float g_agg[(size_t)MAX_ATOMS * FDIM];
__device__ float g_bond_sum[FDIM];
__device__ float g_atom_sum[FDIM];

// ---------------- packed f32x2 helpers (sm_103a) ----------------
__device__ __forceinline__ unsigned long long pack2(float x) {
    unsigned long long r;
    asm("mov.b64 %0, {%1, %1};" : "=l"(r) : "f"(x));
    return r;
}
__device__ __forceinline__ void fma2(unsigned long long &c, unsigned long long a,
                                     unsigned long long b) {
    asm("fma.rn.f32x2 %0, %1, %2, %0;" : "+l"(c) : "l"(a), "l"(b));
}
__device__ __forceinline__ float2 unpack2(unsigned long long v) {
    float2 f;
    asm("mov.b64 {%0, %1}, %2;" : "=f"(f.x), "=f"(f.y) : "l"(v));
    return f;
}
__device__ __forceinline__ float softplus_f(float x) {
    // jax.nn.softplus == logaddexp(x, 0) == max(x,0) + log1p(exp(-|x|))
    return fmaxf(x, 0.f) + log1pf(expf(-fabsf(x)));
}

// ---------------- init scratch sums ----------------
__global__ void init_kernel() {
    int t = threadIdx.x;
    if (t < FDIM) { g_bond_sum[t] = 0.f; g_atom_sum[t] = 0.f; }
}

// ---------------- fused 2-layer MLP over gathered/concatenated inputs ------
// MODE 0 (bonds): comb = [atom_f[i], atom_f[j], bond_f[row], g]
// MODE 1 (atoms): comb = [atom_f[row], agg[row], atom_f[row], g]
// out = softplus(comb @ W1 + b1) @ W2 + b2 + resid[row]
// Also accumulates column sums of out into g_{bond,atom}_sum (for pooling).
//
// Block computes a BM x HID hidden tile then a BM x FDIM output tile.
// 256 threads: 16x16 grid, 8x8 micro-tile (layer1) / 8x4 (layer2),
// inner products done with packed fma.rn.f32x2.
template <int MODE>
__global__ __launch_bounds__(256, 2) void mlp_kernel(
    const float* __restrict__ atom_f,
    const float* __restrict__ bond_f,      // MODE 0 only (bond features)
    const float* __restrict__ gfeat,
    const float* __restrict__ W1, const float* __restrict__ b1,
    const float* __restrict__ W2, const float* __restrict__ b2,
    const int*   __restrict__ ab_idx,      // MODE 0 only
    const float* __restrict__ resid,
    float* __restrict__ outp,
    int n_rows)
{
    extern __shared__ __align__(16) char smem_raw[];
    float* Hs    = (float*)smem_raw;            // [BM][HID+4]  (132 stride)
    float* As    = Hs  + BM * (HID + 4);        // [BK][BM+4]   (132 stride)
    float* Bs    = As  + BK * (BM + 4);         // [BK][HID]
    float* W2s   = Bs  + BK * HID;              // [HID][FDIM]
    int*   iidx  = (int*)(W2s + HID * FDIM);    // [BM]
    int*   jidx  = iidx + BM;                   // [BM]
    float* bias1 = (float*)(jidx + BM);         // [HID]
    float* bias2 = bias1 + HID;                 // [FDIM]
    float* colsum= bias2 + FDIM;                // [FDIM]

    const int tid = threadIdx.x;
    const int row_base = blockIdx.x * BM;

    // Stage weights / bias / indices.
    for (int t = tid; t < HID * FDIM / 4; t += 256)
        ((float4*)W2s)[t] = ((const float4*)W2)[t];
    if (tid < HID) bias1[tid] = b1[tid];
    if (tid < FDIM) { bias2[tid] = b2[tid]; colsum[tid] = 0.f; }
    if (MODE == 0 && tid < BM) {
        int r = row_base + tid;
        if (r >= n_rows) r = n_rows - 1;
        iidx[tid] = ab_idx[2 * r];
        jidx[tid] = ab_idx[2 * r + 1];
    }

    const int ty = tid >> 4, tx = tid & 15;
    const int row0 = ty * 8, c0 = tx * 8;
    const int arow = tid >> 1, ahalf = (tid & 1) << 2;

    unsigned long long acc[8][4];
#pragma unroll
    for (int i = 0; i < 8; i++)
#pragma unroll
        for (int j = 0; j < 4; j++) acc[i][j] = 0ULL;

    __syncthreads();

    int grow = row_base + arow;
    int growc = grow < n_rows ? grow : (n_rows - 1);

    // ---- layer 1: k over 4*FDIM = 256 in BK chunks ----
    for (int kc = 0; kc < 4 * FDIM; kc += BK) {
        const int reg = kc >> 6;
        const int off = (kc & 63) + ahalf;
        const float* src;
        if (MODE == 0) {
            if (reg == 0)      src = atom_f + (size_t)iidx[arow] * FDIM;
            else if (reg == 1) src = atom_f + (size_t)jidx[arow] * FDIM;
            else if (reg == 2) src = bond_f + (size_t)growc * FDIM;
            else               src = gfeat;
        } else {
            if (reg == 1)      src = g_agg  + (size_t)growc * FDIM;
            else if (reg == 3) src = gfeat;
            else               src = atom_f + (size_t)growc * FDIM;
        }
        const float4 av = *(const float4*)(src + off);
        const float4 bv = ((const float4*)(W1 + (size_t)kc * HID))[tid];

        __syncthreads();   // previous tile fully consumed
        As[(ahalf + 0) * (BM + 4) + arow] = av.x;
        As[(ahalf + 1) * (BM + 4) + arow] = av.y;
        As[(ahalf + 2) * (BM + 4) + arow] = av.z;
        As[(ahalf + 3) * (BM + 4) + arow] = av.w;
        ((float4*)Bs)[tid] = bv;
        __syncthreads();   // tile visible

#pragma unroll
        for (int kk = 0; kk < BK; kk++) {
            const float4 a0 = *(const float4*)&As[kk * (BM + 4) + row0];
            const float4 a1 = *(const float4*)&As[kk * (BM + 4) + row0 + 4];
            const ulonglong2 bq0 = *(const ulonglong2*)&Bs[kk * HID + c0];
            const ulonglong2 bq1 = *(const ulonglong2*)&Bs[kk * HID + c0 + 4];
            unsigned long long ap[8];
            ap[0] = pack2(a0.x); ap[1] = pack2(a0.y);
            ap[2] = pack2(a0.z); ap[3] = pack2(a0.w);
            ap[4] = pack2(a1.x); ap[5] = pack2(a1.y);
            ap[6] = pack2(a1.z); ap[7] = pack2(a1.w);
#pragma unroll
            for (int i = 0; i < 8; i++) {
                fma2(acc[i][0], ap[i], bq0.x);
                fma2(acc[i][1], ap[i], bq0.y);
                fma2(acc[i][2], ap[i], bq1.x);
                fma2(acc[i][3], ap[i], bq1.y);
            }
        }
    }

    // ---- bias + softplus -> Hs ----
#pragma unroll
    for (int i = 0; i < 8; i++) {
#pragma unroll
        for (int j = 0; j < 4; j++) {
            float2 v = unpack2(acc[i][j]);
            float h0 = softplus_f(v.x + bias1[c0 + 2 * j]);
            float h1 = softplus_f(v.y + bias1[c0 + 2 * j + 1]);
            *(float2*)&Hs[(row0 + i) * (HID + 4) + c0 + 2 * j] = make_float2(h0, h1);
        }
    }
    __syncthreads();

    // ---- layer 2: [BM x HID] @ [HID x FDIM]; thread owns 8 rows x 4 cols ----
    const int oc0 = tx * 4;
    unsigned long long acc2[8][2];
#pragma unroll
    for (int i = 0; i < 8; i++) { acc2[i][0] = 0ULL; acc2[i][1] = 0ULL; }

#pragma unroll 4
    for (int k = 0; k < HID; k++) {
        const ulonglong2 b = *(const ulonglong2*)&W2s[k * FDIM + oc0];
#pragma unroll
        for (int i = 0; i < 8; i++) {
            unsigned long long a = pack2(Hs[(row0 + i) * (HID + 4) + k]);
            fma2(acc2[i][0], a, b.x);
            fma2(acc2[i][1], a, b.y);
        }
    }

    // ---- bias + residual + store + column partial sums ----
    float rsum0 = 0.f, rsum1 = 0.f, rsum2 = 0.f, rsum3 = 0.f;
#pragma unroll
    for (int i = 0; i < 8; i++) {
        int r = row_base + row0 + i;
        if (r < n_rows) {
            float2 v0 = unpack2(acc2[i][0]);
            float2 v1 = unpack2(acc2[i][1]);
            const float4 rv = *(const float4*)&resid[(size_t)r * FDIM + oc0];
            float4 o;
            o.x = v0.x + bias2[oc0 + 0] + rv.x;
            o.y = v0.y + bias2[oc0 + 1] + rv.y;
            o.z = v1.x + bias2[oc0 + 2] + rv.z;
            o.w = v1.y + bias2[oc0 + 3] + rv.w;
            *(float4*)&outp[(size_t)r * FDIM + oc0] = o;
            rsum0 += o.x; rsum1 += o.y; rsum2 += o.z; rsum3 += o.w;
        }
    }
    atomicAdd(&colsum[oc0 + 0], rsum0);
    atomicAdd(&colsum[oc0 + 1], rsum1);
    atomicAdd(&colsum[oc0 + 2], rsum2);
    atomicAdd(&colsum[oc0 + 3], rsum3);
    __syncthreads();
    if (tid < FDIM) {
        float* gsum = (MODE == 0) ? g_bond_sum : g_atom_sum;
        atomicAdd(&gsum[tid], colsum[tid]);
    }
}

// ---------------- bond -> atom masked mean aggregation ----------------
__global__ void agg_kernel(const float* __restrict__ ub,
                           const int* __restrict__ bai,
                           int n_atoms, int max_deg)
{
    int warp = (blockIdx.x * blockDim.x + threadIdx.x) >> 5;
    int lane = threadIdx.x & 31;
    if (warp >= n_atoms) return;
    int myidx = (lane < max_deg) ? bai[(size_t)warp * max_deg + lane] : -1;
    unsigned mb = __ballot_sync(0xffffffffu, myidx >= 0);
    int cnt = __popc(mb);
    float2 s = make_float2(0.f, 0.f);
#pragma unroll 4
    for (int d = 0; d < 32; d++) {
        if (d >= max_deg) break;
        int idx = __shfl_sync(0xffffffffu, myidx, d);
        if (idx >= 0) {
            float2 v = *(const float2*)&ub[(size_t)idx * FDIM + lane * 2];
            s.x += v.x; s.y += v.y;
        }
    }
    float inv = 1.f / fmaxf((float)cnt, 1.f);
    *(float2*)&g_agg[(size_t)warp * FDIM + lane * 2] = make_float2(s.x * inv, s.y * inv);
}

// ---------------- global MLP ----------------
__global__ void global_kernel(const float* __restrict__ gfeat,
                              const float* __restrict__ Wg1, const float* __restrict__ bg1,
                              const float* __restrict__ Wg2, const float* __restrict__ bg2,
                              float* __restrict__ outg,
                              float n_atoms_f, float n_bonds_f)
{
    __shared__ float comb[3 * FDIM];
    __shared__ float h[HID];
    int t = threadIdx.x;  // 192 threads
    if (t < FDIM)            comb[t] = g_atom_sum[t] / n_atoms_f;
    else if (t < 2 * FDIM)   comb[t] = g_bond_sum[t - FDIM] / n_bonds_f;
    else if (t < 3 * FDIM)   comb[t] = gfeat[t - 2 * FDIM];
    __syncthreads();
    if (t < HID) {
        float a = bg1[t];
#pragma unroll 4
        for (int k = 0; k < 3 * FDIM; k++) a += comb[k] * Wg1[(size_t)k * HID + t];
        h[t] = softplus_f(a);
    }
    __syncthreads();
    if (t < FDIM) {
        float a = bg2[t] + gfeat[t];
#pragma unroll 4
        for (int k = 0; k < HID; k++) a += h[k] * Wg2[(size_t)k * FDIM + t];
        outg[t] = a;
    }
}

// ---------------- launch ----------------
extern "C" void kernel_launch(void* const* d_in, const int* in_sizes, int n_in,
                              void* d_out, int out_size)
{
    const float* atom_f = (const float*)d_in[0];
    const float* bond_f = (const float*)d_in[1];
    const float* gfeat  = (const float*)d_in[2];
    const float* Wb1 = (const float*)d_in[3];
    const float* bb1 = (const float*)d_in[4];
    const float* Wb2 = (const float*)d_in[5];
    const float* bb2 = (const float*)d_in[6];
    const float* Wa1 = (const float*)d_in[7];
    const float* ba1 = (const float*)d_in[8];
    const float* Wa2 = (const float*)d_in[9];
    const float* ba2 = (const float*)d_in[10];
    const float* Wg1 = (const float*)d_in[11];
    const float* bg1 = (const float*)d_in[12];
    const float* Wg2 = (const float*)d_in[13];
    const float* bg2 = (const float*)d_in[14];
    const int* ab_idx = (const int*)d_in[15];
    const int* ba_idx = (const int*)d_in[16];

    const int n_atoms = in_sizes[0] / FDIM;
    const int n_bonds = in_sizes[1] / FDIM;
    const int max_deg = in_sizes[16] / n_atoms;

    float* out        = (float*)d_out;
    float* out_atoms  = out;
    float* out_bonds  = out + (size_t)n_atoms * FDIM;
    float* out_glob   = out + (size_t)n_atoms * FDIM + (size_t)n_bonds * FDIM;

    // dynamic smem: Hs + As + Bs + W2s + idx/bias/colsum
    const size_t SMEM_SZ =
        (size_t)(BM * (HID + 4) + BK * (BM + 4) + BK * HID + HID * FDIM) * 4 +
        (size_t)(BM * 2) * 4 + (size_t)(HID + FDIM + FDIM) * 4;

    cudaFuncSetAttribute(mlp_kernel<0>, cudaFuncAttributeMaxDynamicSharedMemorySize,
                         (int)SMEM_SZ);
    cudaFuncSetAttribute(mlp_kernel<1>, cudaFuncAttributeMaxDynamicSharedMemorySize,
                         (int)SMEM_SZ);

    init_kernel<<<1, 128>>>();

    const int bond_blocks = (n_bonds + BM - 1) / BM;
    mlp_kernel<0><<<bond_blocks, 256, SMEM_SZ>>>(
        atom_f, bond_f, gfeat, Wb1, bb1, Wb2, bb2, ab_idx,
        /*resid=*/bond_f, out_bonds, n_bonds);

    const int agg_blocks = ((n_atoms * 32) + 255) / 256;
    agg_kernel<<<agg_blocks, 256>>>(out_bonds, ba_idx, n_atoms, max_deg);

    const int atom_blocks = (n_atoms + BM - 1) / BM;
    mlp_kernel<1><<<atom_blocks, 256, SMEM_SZ>>>(
        atom_f, /*bond_f=*/nullptr, gfeat, Wa1, ba1, Wa2, ba2, /*ab_idx=*/nullptr,
        /*resid=*/atom_f, out_atoms, n_atoms);

    global_kernel<<<1, 192>>>(gfeat, Wg1, bg1, Wg2, bg2, out_glob,
                              (float)n_atoms, (float)n_bonds);
}

// round 6
// speedup vs baseline: 1.5975x; 1.5975x over previous
#include <cuda_runtime.h>
#include <cuda_fp16.h>
#include <math.h>
#include <stdint.h>

#define FDIM 64
#define HID  128
#define MAX_ATOMS 100000

// ---------------- device scratch (no allocs allowed) ----------------
__device__ float g_agg[(size_t)MAX_ATOMS * FDIM];
__device__ float g_bond_sum[FDIM];
__device__ float g_atom_sum[FDIM];
// pre-transposed fp16 weight images: W^T stored [N][K] row-major
__device__ __align__(16) unsigned short wb1_img[HID * 4 * FDIM];   // [128][256]
__device__ __align__(16) unsigned short wb2_img[FDIM * HID];       // [64][128]
__device__ __align__(16) unsigned short wa1_img[HID * 4 * FDIM];
__device__ __align__(16) unsigned short wa2_img[FDIM * HID];

// ---------------- helpers ----------------
__device__ __forceinline__ float softplus_f(float x) {
    return fmaxf(x, 0.f) + log1pf(expf(-fabsf(x)));
}
__device__ __forceinline__ uint32_t pack_h2(float a, float b) {
    __half2 h = __floats2half2_rn(a, b);
    return *(uint32_t*)&h;
}
__device__ __forceinline__ uint32_t smem_u32(const void* p) {
    uint32_t a;
    asm("{ .reg .u64 t; cvta.to.shared.u64 t, %1; cvt.u32.u64 %0, t; }"
        : "=r"(a) : "l"(p));
    return a;
}
__device__ __forceinline__ void ldm_x4(uint32_t (&r)[4], uint32_t addr) {
    asm volatile("ldmatrix.sync.aligned.m8n8.x4.shared.b16 {%0,%1,%2,%3}, [%4];"
                 : "=r"(r[0]), "=r"(r[1]), "=r"(r[2]), "=r"(r[3]) : "r"(addr));
}
__device__ __forceinline__ void mma16816(float (&d)[4], const uint32_t (&a)[4],
                                         uint32_t b0, uint32_t b1) {
    asm volatile("mma.sync.aligned.m16n8k16.row.col.f32.f16.f16.f32 "
                 "{%0,%1,%2,%3}, {%4,%5,%6,%7}, {%8,%9}, {%0,%1,%2,%3};"
                 : "+f"(d[0]), "+f"(d[1]), "+f"(d[2]), "+f"(d[3])
                 : "r"(a[0]), "r"(a[1]), "r"(a[2]), "r"(a[3]), "r"(b0), "r"(b1));
}

// ---------------- init ----------------
__global__ void init_kernel() {
    int t = threadIdx.x;
    if (t < FDIM) { g_bond_sum[t] = 0.f; g_atom_sum[t] = 0.f; }
}

// ---------------- weight transpose + fp16 convert ----------------
__global__ void prep_weights(const float* __restrict__ W1, const float* __restrict__ W2,
                             unsigned short* __restrict__ img1,
                             unsigned short* __restrict__ img2) {
    int idx = blockIdx.x * blockDim.x + threadIdx.x;
    if (idx < HID * 4 * FDIM) {                 // W1^T [128][256]
        int n = idx >> 8, k = idx & 255;
        __half h = __float2half_rn(W1[(size_t)k * HID + n]);
        img1[idx] = *(unsigned short*)&h;
    } else if (idx < HID * 4 * FDIM + FDIM * HID) {  // W2^T [64][128]
        int t = idx - HID * 4 * FDIM;
        int n = t >> 7, k = t & 127;
        __half h = __float2half_rn(W2[(size_t)k * FDIM + n]);
        img2[t] = *(unsigned short*)&h;
    }
}

// ---------------- SMEM layout (bytes) ----------------
// A  : 128 rows x (256+8) halves, stride 528 B
// W1T: 128 rows x (256+8) halves, stride 528 B
// H  : 128 rows x (128+8) halves, stride 272 B
// W2T:  64 rows x (128+8) halves, stride 272 B
static constexpr int ASTRIDE = 528;
static constexpr int HSTRIDE = 272;
static constexpr int SM_A  = 0;
static constexpr int SM_W1 = SM_A + 128 * ASTRIDE;       // 67584
static constexpr int SM_H  = SM_W1 + 128 * ASTRIDE;      // 135168
static constexpr int SM_W2 = SM_H + 128 * HSTRIDE;       // 169984
static constexpr int SM_B1 = SM_W2 + 64 * HSTRIDE;       // 187392
static constexpr int SM_B2 = SM_B1 + 512;                // 187904
static constexpr int SM_CS = SM_B2 + 256;                // 188160
static constexpr int SMEM_SZ = SM_CS + 256;              // 188416

// ---------------- fused 2-layer MLP on mma.sync tensor cores -----------
// MODE 0 (bonds): comb = [atom_f[i], atom_f[j], bond_f[row], g]
// MODE 1 (atoms): comb = [atom_f[row], g_agg[row], atom_f[row], g]
template <int MODE>
__global__ __launch_bounds__(256, 1)
void mlp_tc(const float* __restrict__ atom_f,
            const float* __restrict__ bond_f,
            const float* __restrict__ gfeat,
            const float* __restrict__ b1, const float* __restrict__ b2,
            const int*   __restrict__ ab_idx,
            const float* __restrict__ resid,
            const unsigned short* __restrict__ w1img,
            const unsigned short* __restrict__ w2img,
            float* __restrict__ outp,
            int n_rows)
{
    extern __shared__ __align__(16) char smem[];
    const uint32_t sb = smem_u32(smem);
    float* bias1  = (float*)(smem + SM_B1);
    float* bias2  = (float*)(smem + SM_B2);
    float* colsum = (float*)(smem + SM_CS);

    const int tid = threadIdx.x, wid = tid >> 5, lane = tid & 31;
    const int row_base = blockIdx.x * 128;
    const int warp_m = wid >> 1, warp_n = wid & 1;

    // stage weights (pad stride) + biases + zero colsum
    for (int i = tid; i < 4096; i += 256) {               // W1T: 128 rows x 32 uint4
        int r = i >> 5, c = i & 31;
        *(uint4*)(smem + SM_W1 + r * ASTRIDE + c * 16) = ((const uint4*)w1img)[i];
    }
    for (int i = tid; i < 1024; i += 256) {               // W2T: 64 rows x 16 uint4
        int r = i >> 4, c = i & 15;
        *(uint4*)(smem + SM_W2 + r * HSTRIDE + c * 16) = ((const uint4*)w2img)[i];
    }
    if (tid < HID)  bias1[tid] = b1[tid];
    if (tid < FDIM) { bias2[tid] = b2[tid]; colsum[tid] = 0.f; }

    // ---- gather + fp16 convert of A [128 x 256] ----
    {
        const int row = tid >> 1, hsel = tid & 1;
        int gr = row_base + row;
        int grc = gr < n_rows ? gr : n_rows - 1;
        const float* seg_src[2];
        if (MODE == 0) {
            if (hsel == 0) {
                int i0 = ab_idx[2 * grc], j0 = ab_idx[2 * grc + 1];
                seg_src[0] = atom_f + (size_t)i0 * FDIM;
                seg_src[1] = atom_f + (size_t)j0 * FDIM;
            } else {
                seg_src[0] = bond_f + (size_t)grc * FDIM;
                seg_src[1] = gfeat;
            }
        } else {
            if (hsel == 0) {
                seg_src[0] = atom_f + (size_t)grc * FDIM;
                seg_src[1] = g_agg + (size_t)grc * FDIM;
            } else {
                seg_src[0] = atom_f + (size_t)grc * FDIM;
                seg_src[1] = gfeat;
            }
        }
#pragma unroll
        for (int seg = 0; seg < 2; seg++) {
            char* dst = smem + SM_A + row * ASTRIDE + hsel * 256 + seg * 128;
            const float4* s4 = (const float4*)seg_src[seg];
#pragma unroll
            for (int q = 0; q < 16; q++) {
                float4 v = s4[q];
                *(uint32_t*)(dst + q * 8)     = pack_h2(v.x, v.y);
                *(uint32_t*)(dst + q * 8 + 4) = pack_h2(v.z, v.w);
            }
        }
    }
    __syncthreads();

    // ldmatrix lane-address components
    const uint32_t aLane1 = (uint32_t)((lane & 15) * ASTRIDE + (lane >> 4) * 16);
    const uint32_t aLane2 = (uint32_t)((lane & 15) * HSTRIDE + (lane >> 4) * 16);
    const uint32_t bN   = (uint32_t)((lane & 7) + ((lane >> 4) << 3));
    const uint32_t bK   = (uint32_t)(((lane >> 3) & 1) * 16);

    // ---- layer 1: C1[32x128-slice] = A @ W1T^T ----
    float c1[2][8][4];
#pragma unroll
    for (int mi = 0; mi < 2; mi++)
#pragma unroll
        for (int nb = 0; nb < 8; nb++)
#pragma unroll
            for (int j = 0; j < 4; j++) c1[mi][nb][j] = 0.f;

    const uint32_t aBase1 = sb + SM_A + (uint32_t)(warp_m * 32) * ASTRIDE + aLane1;
    const uint32_t bBase1 = sb + SM_W1 + (uint32_t)(warp_n * 64 + bN) * ASTRIDE + bK;
#pragma unroll
    for (int k0 = 0; k0 < 256; k0 += 16) {
        uint32_t a[2][4];
        ldm_x4(a[0], aBase1 + k0 * 2);
        ldm_x4(a[1], aBase1 + 16 * ASTRIDE + k0 * 2);
#pragma unroll
        for (int g = 0; g < 4; g++) {      // each g covers 2 n8-tiles
            uint32_t bf[4];
            ldm_x4(bf, bBase1 + (uint32_t)(g * 16) * ASTRIDE + k0 * 2);
            mma16816(c1[0][2 * g],     a[0], bf[0], bf[1]);
            mma16816(c1[0][2 * g + 1], a[0], bf[2], bf[3]);
            mma16816(c1[1][2 * g],     a[1], bf[0], bf[1]);
            mma16816(c1[1][2 * g + 1], a[1], bf[2], bf[3]);
        }
    }

    // ---- epilogue 1: bias + softplus -> fp16 H ----
    {
        const int r0 = warp_m * 32 + (lane >> 2);
        const int cb = warp_n * 64 + (lane & 3) * 2;
#pragma unroll
        for (int mi = 0; mi < 2; mi++) {
#pragma unroll
            for (int nb = 0; nb < 8; nb++) {
                int col = cb + nb * 8;
                float b0v = bias1[col], b1v = bias1[col + 1];
                uint32_t p0 = pack_h2(softplus_f(c1[mi][nb][0] + b0v),
                                      softplus_f(c1[mi][nb][1] + b1v));
                uint32_t p1 = pack_h2(softplus_f(c1[mi][nb][2] + b0v),
                                      softplus_f(c1[mi][nb][3] + b1v));
                int row = r0 + mi * 16;
                *(uint32_t*)(smem + SM_H + row * HSTRIDE + col * 2) = p0;
                *(uint32_t*)(smem + SM_H + (row + 8) * HSTRIDE + col * 2) = p1;
            }
        }
    }
    __syncthreads();

    // ---- layer 2: C2[32x32-slice] = H @ W2T^T ----
    float c2[2][4][4];
#pragma unroll
    for (int mi = 0; mi < 2; mi++)
#pragma unroll
        for (int nb = 0; nb < 4; nb++)
#pragma unroll
            for (int j = 0; j < 4; j++) c2[mi][nb][j] = 0.f;

    const uint32_t aBase2 = sb + SM_H + (uint32_t)(warp_m * 32) * HSTRIDE + aLane2;
    const uint32_t bBase2 = sb + SM_W2 + (uint32_t)(warp_n * 32 + bN) * HSTRIDE + bK;
#pragma unroll
    for (int k0 = 0; k0 < 128; k0 += 16) {
        uint32_t a[2][4];
        ldm_x4(a[0], aBase2 + k0 * 2);
        ldm_x4(a[1], aBase2 + 16 * HSTRIDE + k0 * 2);
#pragma unroll
        for (int g = 0; g < 2; g++) {
            uint32_t bf[4];
            ldm_x4(bf, bBase2 + (uint32_t)(g * 16) * HSTRIDE + k0 * 2);
            mma16816(c2[0][2 * g],     a[0], bf[0], bf[1]);
            mma16816(c2[0][2 * g + 1], a[0], bf[2], bf[3]);
            mma16816(c2[1][2 * g],     a[1], bf[0], bf[1]);
            mma16816(c2[1][2 * g + 1], a[1], bf[2], bf[3]);
        }
    }

    // ---- epilogue 2: bias + residual + store + column sums ----
    {
        const int cb = warp_n * 32 + (lane & 3) * 2;
        float ls[4][2];
#pragma unroll
        for (int nb = 0; nb < 4; nb++) { ls[nb][0] = 0.f; ls[nb][1] = 0.f; }
#pragma unroll
        for (int mi = 0; mi < 2; mi++) {
#pragma unroll
            for (int half = 0; half < 2; half++) {
                int row = warp_m * 32 + mi * 16 + half * 8 + (lane >> 2);
                int grow = row_base + row;
                if (grow < n_rows) {
#pragma unroll
                    for (int nb = 0; nb < 4; nb++) {
                        int col = cb + nb * 8;
                        float v0 = c2[mi][nb][half * 2 + 0] + bias2[col];
                        float v1 = c2[mi][nb][half * 2 + 1] + bias2[col + 1];
                        const float2 rv = *(const float2*)&resid[(size_t)grow * FDIM + col];
                        float2 o = make_float2(v0 + rv.x, v1 + rv.y);
                        *(float2*)&outp[(size_t)grow * FDIM + col] = o;
                        ls[nb][0] += o.x; ls[nb][1] += o.y;
                    }
                }
            }
        }
#pragma unroll
        for (int nb = 0; nb < 4; nb++) {
            atomicAdd(&colsum[cb + nb * 8],     ls[nb][0]);
            atomicAdd(&colsum[cb + nb * 8 + 1], ls[nb][1]);
        }
    }
    __syncthreads();
    if (tid < FDIM) {
        float* gsum = (MODE == 0) ? g_bond_sum : g_atom_sum;
        atomicAdd(&gsum[tid], colsum[tid]);
    }
}

// ---------------- bond -> atom masked mean aggregation ----------------
__global__ void agg_kernel(const float* __restrict__ ub,
                           const int* __restrict__ bai,
                           int n_atoms, int max_deg)
{
    int warp = (blockIdx.x * blockDim.x + threadIdx.x) >> 5;
    int lane = threadIdx.x & 31;
    if (warp >= n_atoms) return;
    int myidx = (lane < max_deg) ? bai[(size_t)warp * max_deg + lane] : -1;
    unsigned mb = __ballot_sync(0xffffffffu, myidx >= 0);
    int cnt = __popc(mb);
    float2 s = make_float2(0.f, 0.f);
#pragma unroll 4
    for (int d = 0; d < 32; d++) {
        if (d >= max_deg) break;
        int idx = __shfl_sync(0xffffffffu, myidx, d);
        if (idx >= 0) {
            float2 v = *(const float2*)&ub[(size_t)idx * FDIM + lane * 2];
            s.x += v.x; s.y += v.y;
        }
    }
    float inv = 1.f / fmaxf((float)cnt, 1.f);
    *(float2*)&g_agg[(size_t)warp * FDIM + lane * 2] = make_float2(s.x * inv, s.y * inv);
}

// ---------------- global MLP ----------------
__global__ void global_kernel(const float* __restrict__ gfeat,
                              const float* __restrict__ Wg1, const float* __restrict__ bg1,
                              const float* __restrict__ Wg2, const float* __restrict__ bg2,
                              float* __restrict__ outg,
                              float n_atoms_f, float n_bonds_f)
{
    __shared__ float comb[3 * FDIM];
    __shared__ float h[HID];
    int t = threadIdx.x;  // 192 threads
    if (t < FDIM)            comb[t] = g_atom_sum[t] / n_atoms_f;
    else if (t < 2 * FDIM)   comb[t] = g_bond_sum[t - FDIM] / n_bonds_f;
    else if (t < 3 * FDIM)   comb[t] = gfeat[t - 2 * FDIM];
    __syncthreads();
    if (t < HID) {
        float a = bg1[t];
#pragma unroll 4
        for (int k = 0; k < 3 * FDIM; k++) a += comb[k] * Wg1[(size_t)k * HID + t];
        h[t] = softplus_f(a);
    }
    __syncthreads();
    if (t < FDIM) {
        float a = bg2[t] + gfeat[t];
#pragma unroll 4
        for (int k = 0; k < HID; k++) a += h[k] * Wg2[(size_t)k * FDIM + t];
        outg[t] = a;
    }
}

// ---------------- launch ----------------
extern "C" void kernel_launch(void* const* d_in, const int* in_sizes, int n_in,
                              void* d_out, int out_size)
{
    const float* atom_f = (const float*)d_in[0];
    const float* bond_f = (const float*)d_in[1];
    const float* gfeat  = (const float*)d_in[2];
    const float* Wb1 = (const float*)d_in[3];
    const float* bb1 = (const float*)d_in[4];
    const float* Wb2 = (const float*)d_in[5];
    const float* bb2 = (const float*)d_in[6];
    const float* Wa1 = (const float*)d_in[7];
    const float* ba1 = (const float*)d_in[8];
    const float* Wa2 = (const float*)d_in[9];
    const float* ba2 = (const float*)d_in[10];
    const float* Wg1 = (const float*)d_in[11];
    const float* bg1 = (const float*)d_in[12];
    const float* Wg2 = (const float*)d_in[13];
    const float* bg2 = (const float*)d_in[14];
    const int* ab_idx = (const int*)d_in[15];
    const int* ba_idx = (const int*)d_in[16];

    const int n_atoms = in_sizes[0] / FDIM;
    const int n_bonds = in_sizes[1] / FDIM;
    const int max_deg = in_sizes[16] / n_atoms;

    float* out       = (float*)d_out;
    float* out_atoms = out;
    float* out_bonds = out + (size_t)n_atoms * FDIM;
    float* out_glob  = out + (size_t)n_atoms * FDIM + (size_t)n_bonds * FDIM;

    cudaFuncSetAttribute(mlp_tc<0>, cudaFuncAttributeMaxDynamicSharedMemorySize, SMEM_SZ);
    cudaFuncSetAttribute(mlp_tc<1>, cudaFuncAttributeMaxDynamicSharedMemorySize, SMEM_SZ);

    unsigned short *pwb1, *pwb2, *pwa1, *pwa2;
    cudaGetSymbolAddress((void**)&pwb1, wb1_img);
    cudaGetSymbolAddress((void**)&pwb2, wb2_img);
    cudaGetSymbolAddress((void**)&pwa1, wa1_img);
    cudaGetSymbolAddress((void**)&pwa2, wa2_img);

    init_kernel<<<1, 128>>>();

    const int prep_elems = HID * 4 * FDIM + FDIM * HID;   // 40960
    prep_weights<<<(prep_elems + 255) / 256, 256>>>(Wb1, Wb2, pwb1, pwb2);
    prep_weights<<<(prep_elems + 255) / 256, 256>>>(Wa1, Wa2, pwa1, pwa2);

    const int bond_blocks = (n_bonds + 127) / 128;
    mlp_tc<0><<<bond_blocks, 256, SMEM_SZ>>>(
        atom_f, bond_f, gfeat, bb1, bb2, ab_idx,
        /*resid=*/bond_f, pwb1, pwb2, out_bonds, n_bonds);

    const int agg_blocks = ((n_atoms * 32) + 255) / 256;
    agg_kernel<<<agg_blocks, 256>>>(out_bonds, ba_idx, n_atoms, max_deg);

    const int atom_blocks = (n_atoms + 127) / 128;
    mlp_tc<1><<<atom_blocks, 256, SMEM_SZ>>>(
        atom_f, /*bond_f=*/nullptr, gfeat, ba1, ba2, /*ab_idx=*/nullptr,
        /*resid=*/atom_f, pwa1, pwa2, out_atoms, n_atoms);

    global_kernel<<<1, 192>>>(gfeat, Wg1, bg1, Wg2, bg2, out_glob,
                              (float)n_atoms, (float)n_bonds);
}

// round 8
// speedup vs baseline: 3.0083x; 1.8831x over previous
#include <cuda_runtime.h>
#include <cuda_fp16.h>
#include <math.h>
#include <stdint.h>

#define FDIM 64
#define HID  128
#define N_ATOMS_MAX 100000
#define N_BONDS_MAX 800000

// ---------------- device scratch (no allocs allowed) ----------------
__device__ float g_bond_sum[FDIM];
__device__ float g_atom_sum[FDIM];
__device__ __align__(16) unsigned short g_atom_h[(size_t)N_ATOMS_MAX * FDIM]; // fp16 atom feats
__device__ __align__(16) unsigned short g_agg_h [(size_t)N_ATOMS_MAX * FDIM]; // fp16 agg
__device__ __align__(16) unsigned short g_bond_h[(size_t)N_BONDS_MAX * FDIM]; // fp16 updated bonds
__device__ __align__(16) unsigned short g_h_dev[FDIM];                        // fp16 global feats
// pre-transposed fp16 weight images: W^T stored [N][K] row-major
__device__ __align__(16) unsigned short wb1_img[HID * 4 * FDIM];   // [128][256]
__device__ __align__(16) unsigned short wb2_img[FDIM * HID];       // [64][128]
__device__ __align__(16) unsigned short wa1_img[HID * 4 * FDIM];
__device__ __align__(16) unsigned short wa2_img[FDIM * HID];

// ---------------- helpers ----------------
__device__ __forceinline__ float softplus_f(float x) {
    float t = __expf(-fabsf(x));
    return fmaxf(x, 0.f) + __logf(1.f + t);
}
__device__ __forceinline__ uint32_t pack_h2(float a, float b) {
    __half2 h = __floats2half2_rn(a, b);
    return *(uint32_t*)&h;
}
__device__ __forceinline__ uint32_t smem_u32(const void* p) {
    uint32_t a;
    asm("{ .reg .u64 t; cvta.to.shared.u64 t, %1; cvt.u32.u64 %0, t; }"
        : "=r"(a) : "l"(p));
    return a;
}
__device__ __forceinline__ void ldm_x4(uint32_t (&r)[4], uint32_t addr) {
    asm volatile("ldmatrix.sync.aligned.m8n8.x4.shared.b16 {%0,%1,%2,%3}, [%4];"
                 : "=r"(r[0]), "=r"(r[1]), "=r"(r[2]), "=r"(r[3]) : "r"(addr));
}
__device__ __forceinline__ void mma16816(float (&d)[4], const uint32_t (&a)[4],
                                         uint32_t b0, uint32_t b1) {
    asm volatile("mma.sync.aligned.m16n8k16.row.col.f32.f16.f16.f32 "
                 "{%0,%1,%2,%3}, {%4,%5,%6,%7}, {%8,%9}, {%0,%1,%2,%3};"
                 : "+f"(d[0]), "+f"(d[1]), "+f"(d[2]), "+f"(d[3])
                 : "r"(a[0]), "r"(a[1]), "r"(a[2]), "r"(a[3]), "r"(b0), "r"(b1));
}
__device__ __forceinline__ void cpa16(uint32_t dst, const void* src) {
    asm volatile("cp.async.ca.shared.global [%0], [%1], 16;"
                 :: "r"(dst), "l"(src));
}
__device__ __forceinline__ void cpa_wait_all() {
    asm volatile("cp.async.wait_all;" ::: "memory");
}

// ---------------- init ----------------
__global__ void init_kernel() {
    int t = threadIdx.x;
    if (t < FDIM) { g_bond_sum[t] = 0.f; g_atom_sum[t] = 0.f; }
}

// ---------------- weight transpose + fp16 convert ----------------
__global__ void prep_weights(const float* __restrict__ W1, const float* __restrict__ W2,
                             unsigned short* __restrict__ img1,
                             unsigned short* __restrict__ img2) {
    int idx = blockIdx.x * blockDim.x + threadIdx.x;
    if (idx < HID * 4 * FDIM) {                 // W1^T [128][256]
        int n = idx >> 8, k = idx & 255;
        __half h = __float2half_rn(W1[(size_t)k * HID + n]);
        img1[idx] = *(unsigned short*)&h;
    } else if (idx < HID * 4 * FDIM + FDIM * HID) {  // W2^T [64][128]
        int t = idx - HID * 4 * FDIM;
        int n = t >> 7, k = t & 127;
        __half h = __float2half_rn(W2[(size_t)k * FDIM + n]);
        img2[t] = *(unsigned short*)&h;
    }
}

// ---------------- atom features + gfeat -> fp16 ----------------
__global__ void prep_atom(const float* __restrict__ atom_f,
                          const float* __restrict__ gfeat, int n4) {
    int idx = blockIdx.x * blockDim.x + threadIdx.x;
    if (idx < n4) {
        float4 v = ((const float4*)atom_f)[idx];
        uint2 o = make_uint2(pack_h2(v.x, v.y), pack_h2(v.z, v.w));
        ((uint2*)g_atom_h)[idx] = o;
    }
    if (blockIdx.x == 0 && threadIdx.x < 16) {
        float4 v = ((const float4*)gfeat)[threadIdx.x];
        ((uint2*)g_h_dev)[threadIdx.x] = make_uint2(pack_h2(v.x, v.y), pack_h2(v.z, v.w));
    }
}

// ---------------- SMEM layout (bytes) ----------------
static constexpr int ASTRIDE = 528;   // 256+8 halves
static constexpr int HSTRIDE = 272;   // 128+8 halves
static constexpr int SM_A  = 0;
static constexpr int SM_W1 = SM_A + 128 * ASTRIDE;       // 67584
static constexpr int SM_H  = SM_W1 + 128 * ASTRIDE;      // 135168
static constexpr int SM_W2 = SM_H + 128 * HSTRIDE;       // 169984
static constexpr int SM_B1 = SM_W2 + 64 * HSTRIDE;       // 187392
static constexpr int SM_B2 = SM_B1 + 512;                // 187904
static constexpr int SM_CS = SM_B2 + 256;                // 188160
static constexpr int SM_RES = SM_CS + 256;               // 188416 (128 rows x 256B fp32)
static constexpr int SMEM_SZ = SM_RES + 128 * 256;       // 221184

// ---------------- persistent fused 2-layer MLP (mma.sync) ----------------
// MODE 0 (bonds): comb = [atom_h[i], atom_h[j], f16(bond_f[row]), g_h]
// MODE 1 (atoms): comb = [atom_h[row], agg_h[row], atom_h[row], g_h]
template <int MODE>
__global__ __launch_bounds__(512, 1)
void mlp_tc(const float* __restrict__ resid_glob,   // MODE1: atom_f
            const float* __restrict__ bond_f,       // MODE0 only
            const float* __restrict__ b1, const float* __restrict__ b2,
            const int*   __restrict__ ab_idx,       // MODE0 only
            const unsigned short* __restrict__ w1img,
            const unsigned short* __restrict__ w2img,
            float* __restrict__ outp,
            int n_rows)
{
    extern __shared__ __align__(16) char smem[];
    const uint32_t sb = smem_u32(smem);
    float* bias1  = (float*)(smem + SM_B1);
    float* bias2  = (float*)(smem + SM_B2);
    float* colsum = (float*)(smem + SM_CS);

    const int tid = threadIdx.x, wid = tid >> 5, lane = tid & 31;
    const int warp_m = wid >> 2, warp_n = wid & 3;
    const int n_tiles = (n_rows + 127) >> 7;

    // ---- one-time staging: weights (padded stride), biases, colsum ----
    for (int i = tid; i < 4096; i += 512) {               // W1T: 128 rows x 32 uint4
        int r = i >> 5, c = i & 31;
        *(uint4*)(smem + SM_W1 + r * ASTRIDE + c * 16) = ((const uint4*)w1img)[i];
    }
    for (int i = tid; i < 1024; i += 512) {               // W2T: 64 rows x 16 uint4
        int r = i >> 4, c = i & 15;
        *(uint4*)(smem + SM_W2 + r * HSTRIDE + c * 16) = ((const uint4*)w2img)[i];
    }
    if (tid < HID)  bias1[tid] = b1[tid];
    if (tid < FDIM) { bias2[tid] = b2[tid]; colsum[tid] = 0.f; }

    // gather thread mapping: 4 threads per row
    const int grow_r = tid >> 2, qs = tid & 3;

    // ldmatrix lane-address components
    const uint32_t aLane1 = (uint32_t)((lane & 15) * ASTRIDE + (lane >> 4) * 16);
    const uint32_t aLane2 = (uint32_t)((lane & 15) * HSTRIDE + (lane >> 4) * 16);
    const uint32_t bN = (uint32_t)((lane & 7) + ((lane >> 4) << 3));
    const uint32_t bK = (uint32_t)(((lane >> 3) & 1) * 16);
    const uint32_t aBase1 = sb + SM_A + (uint32_t)(warp_m * 32) * ASTRIDE + aLane1;
    const uint32_t bBase1 = sb + SM_W1 + (uint32_t)(warp_n * 32 + bN) * ASTRIDE + bK;
    const uint32_t aBase2 = sb + SM_H + (uint32_t)(warp_m * 32) * HSTRIDE + aLane2;
    const uint32_t bBase2 = sb + SM_W2 + (uint32_t)(warp_n * 16 + bN) * HSTRIDE + bK;

    float ls[2][2] = {{0.f, 0.f}, {0.f, 0.f}};   // per-thread column sums across tiles

    // async gather of fp16 A segments for a tile
    auto gather_async = [&](int tile) {
        int gr = tile * 128 + grow_r;
        int grc = gr < n_rows ? gr : n_rows - 1;
        const uint32_t dstrow = sb + SM_A + (uint32_t)grow_r * ASTRIDE;
        if (MODE == 0) {
            if (qs == 0) {
                const char* src = (const char*)(g_atom_h + (size_t)ab_idx[2 * grc] * FDIM);
#pragma unroll
                for (int q = 0; q < 8; q++) cpa16(dstrow + q * 16, src + q * 16);
            } else if (qs == 1) {
                const char* src = (const char*)(g_atom_h + (size_t)ab_idx[2 * grc + 1] * FDIM);
#pragma unroll
                for (int q = 0; q < 8; q++) cpa16(dstrow + 128 + q * 16, src + q * 16);
            } else if (qs == 2) {
#pragma unroll
                for (int q = 0; q < 4; q++) cpa16(dstrow + 384 + q * 16, (const char*)g_h_dev + q * 16);
            } else {
#pragma unroll
                for (int q = 0; q < 4; q++) cpa16(dstrow + 448 + q * 16, (const char*)g_h_dev + 64 + q * 16);
            }
        } else {
            const char* arow = (const char*)(g_atom_h + (size_t)grc * FDIM);
            if (qs == 0) {
#pragma unroll
                for (int q = 0; q < 8; q++) cpa16(dstrow + q * 16, arow + q * 16);
            } else if (qs == 1) {
                const char* src = (const char*)(g_agg_h + (size_t)grc * FDIM);
#pragma unroll
                for (int q = 0; q < 8; q++) cpa16(dstrow + 128 + q * 16, src + q * 16);
            } else if (qs == 2) {
#pragma unroll
                for (int q = 0; q < 8; q++) cpa16(dstrow + 256 + q * 16, arow + q * 16);
            } else {
#pragma unroll
                for (int q = 0; q < 8; q++) cpa16(dstrow + 384 + q * 16, (const char*)g_h_dev + q * 16);
            }
        }
    };

    int tile = blockIdx.x;
    if (tile < n_tiles) gather_async(tile);

    for (; tile < n_tiles; tile += gridDim.x) {
        const int row_base = tile * 128;

        // ---- sync part of gather: bond fp32 row -> A seg2 (fp16) + RES (fp32) ----
        if (MODE == 0) {
            int gr = row_base + grow_r;
            int grc = gr < n_rows ? gr : n_rows - 1;
            const float4* bs = (const float4*)(bond_f + (size_t)grc * FDIM) + qs * 4;
            float4 v0 = bs[0], v1 = bs[1], v2 = bs[2], v3 = bs[3];
            char* adst = smem + SM_A + grow_r * ASTRIDE + 256 + qs * 32;
            ((uint4*)adst)[0] = make_uint4(pack_h2(v0.x, v0.y), pack_h2(v0.z, v0.w),
                                           pack_h2(v1.x, v1.y), pack_h2(v1.z, v1.w));
            ((uint4*)adst)[1] = make_uint4(pack_h2(v2.x, v2.y), pack_h2(v2.z, v2.w),
                                           pack_h2(v3.x, v3.y), pack_h2(v3.z, v3.w));
            float4* rdst = (float4*)(smem + SM_RES + grow_r * 256) + qs * 4;
            rdst[0] = v0; rdst[1] = v1; rdst[2] = v2; rdst[3] = v3;
        }
        cpa_wait_all();
        __syncthreads();                        // A(t) complete, W/bias visible

        // ---- layer 1: c1 (32 rows x 32 cols per warp) ----
        float c1[2][4][4];
#pragma unroll
        for (int mi = 0; mi < 2; mi++)
#pragma unroll
            for (int nb = 0; nb < 4; nb++)
#pragma unroll
                for (int j = 0; j < 4; j++) c1[mi][nb][j] = 0.f;

#pragma unroll
        for (int k0 = 0; k0 < 256; k0 += 16) {
            uint32_t a0[4], a1[4];
            ldm_x4(a0, aBase1 + k0 * 2);
            ldm_x4(a1, aBase1 + 16 * ASTRIDE + k0 * 2);
#pragma unroll
            for (int g = 0; g < 2; g++) {
                uint32_t bf[4];
                ldm_x4(bf, bBase1 + (uint32_t)(g * 16) * ASTRIDE + k0 * 2);
                mma16816(c1[0][2 * g],     a0, bf[0], bf[1]);
                mma16816(c1[0][2 * g + 1], a0, bf[2], bf[3]);
                mma16816(c1[1][2 * g],     a1, bf[0], bf[1]);
                mma16816(c1[1][2 * g + 1], a1, bf[2], bf[3]);
            }
        }

        // ---- epilogue 1: bias + softplus -> fp16 H ----
        {
            const int r0 = warp_m * 32 + (lane >> 2);
            const int cb = warp_n * 32 + (lane & 3) * 2;
#pragma unroll
            for (int mi = 0; mi < 2; mi++) {
#pragma unroll
                for (int nb = 0; nb < 4; nb++) {
                    int col = cb + nb * 8;
                    float b0v = bias1[col], b1v = bias1[col + 1];
                    uint32_t p0 = pack_h2(softplus_f(c1[mi][nb][0] + b0v),
                                          softplus_f(c1[mi][nb][1] + b1v));
                    uint32_t p1 = pack_h2(softplus_f(c1[mi][nb][2] + b0v),
                                          softplus_f(c1[mi][nb][3] + b1v));
                    int row = r0 + mi * 16;
                    *(uint32_t*)(smem + SM_H + row * HSTRIDE + col * 2) = p0;
                    *(uint32_t*)(smem + SM_H + (row + 8) * HSTRIDE + col * 2) = p1;
                }
            }
        }
        __syncthreads();                        // H ready; A free for overwrite

        // ---- prefetch next tile's fp16 A segments (overlaps MMA2/epilogue2) ----
        if (tile + (int)gridDim.x < n_tiles) gather_async(tile + gridDim.x);

        // ---- layer 2: c2 (32 rows x 16 cols per warp) ----
        float c2[2][2][4];
#pragma unroll
        for (int mi = 0; mi < 2; mi++)
#pragma unroll
            for (int nb = 0; nb < 2; nb++)
#pragma unroll
                for (int j = 0; j < 4; j++) c2[mi][nb][j] = 0.f;

#pragma unroll
        for (int k0 = 0; k0 < 128; k0 += 16) {
            uint32_t a0[4], a1[4], bf[4];
            ldm_x4(a0, aBase2 + k0 * 2);
            ldm_x4(a1, aBase2 + 16 * HSTRIDE + k0 * 2);
            ldm_x4(bf, bBase2 + k0 * 2);
            mma16816(c2[0][0], a0, bf[0], bf[1]);
            mma16816(c2[0][1], a0, bf[2], bf[3]);
            mma16816(c2[1][0], a1, bf[0], bf[1]);
            mma16816(c2[1][1], a1, bf[2], bf[3]);
        }

        // ---- epilogue 2: bias + residual + stores + running column sums ----
        {
            const int cb2 = warp_n * 16 + (lane & 3) * 2;
#pragma unroll
            for (int mi = 0; mi < 2; mi++) {
#pragma unroll
                for (int half = 0; half < 2; half++) {
                    int row = warp_m * 32 + mi * 16 + half * 8 + (lane >> 2);
                    int grow = row_base + row;
                    if (grow < n_rows) {
#pragma unroll
                        for (int nb = 0; nb < 2; nb++) {
                            int col = cb2 + nb * 8;
                            float v0 = c2[mi][nb][half * 2 + 0] + bias2[col];
                            float v1 = c2[mi][nb][half * 2 + 1] + bias2[col + 1];
                            float2 rv;
                            if (MODE == 0)
                                rv = *(const float2*)(smem + SM_RES + row * 256 + col * 4);
                            else
                                rv = *(const float2*)&resid_glob[(size_t)grow * FDIM + col];
                            float2 o = make_float2(v0 + rv.x, v1 + rv.y);
                            *(float2*)&outp[(size_t)grow * FDIM + col] = o;
                            if (MODE == 0)
                                ((uint32_t*)g_bond_h)[(size_t)grow * 32 + (col >> 1)] =
                                    pack_h2(o.x, o.y);
                            ls[nb][0] += o.x; ls[nb][1] += o.y;
                        }
                    }
                }
            }
        }
        __syncthreads();                        // RES/A reusable next iteration
    }

    // ---- flush column sums ----
#pragma unroll
    for (int nb = 0; nb < 2; nb++) {
        int col = warp_n * 16 + (lane & 3) * 2 + nb * 8;
        atomicAdd(&colsum[col],     ls[nb][0]);
        atomicAdd(&colsum[col + 1], ls[nb][1]);
    }
    __syncthreads();
    if (tid < FDIM) {
        float* gsum = (MODE == 0) ? g_bond_sum : g_atom_sum;
        atomicAdd(&gsum[tid], colsum[tid]);
    }
}

// ---------------- bond -> atom masked mean aggregation (fp16 in/out) -------
__global__ void agg_kernel(const int* __restrict__ bai, int n_atoms, int max_deg)
{
    int warp = (blockIdx.x * blockDim.x + threadIdx.x) >> 5;
    int lane = threadIdx.x & 31;
    if (warp >= n_atoms) return;
    int myidx = (lane < max_deg) ? bai[(size_t)warp * max_deg + lane] : -1;
    unsigned mb = __ballot_sync(0xffffffffu, myidx >= 0);
    int cnt = __popc(mb);
    float sx = 0.f, sy = 0.f;
#pragma unroll 4
    for (int d = 0; d < 32; d++) {
        if (d >= max_deg) break;
        int idx = __shfl_sync(0xffffffffu, myidx, d);
        if (idx >= 0) {
            uint32_t u = ((const uint32_t*)g_bond_h)[(size_t)idx * 32 + lane];
            float2 v = __half22float2(*(__half2*)&u);
            sx += v.x; sy += v.y;
        }
    }
    float inv = 1.f / fmaxf((float)cnt, 1.f);
    ((uint32_t*)g_agg_h)[(size_t)warp * 32 + lane] = pack_h2(sx * inv, sy * inv);
}

// ---------------- global MLP ----------------
__global__ void global_kernel(const float* __restrict__ gfeat,
                              const float* __restrict__ Wg1, const float* __restrict__ bg1,
                              const float* __restrict__ Wg2, const float* __restrict__ bg2,
                              float* __restrict__ outg,
                              float n_atoms_f, float n_bonds_f)
{
    __shared__ float comb[3 * FDIM];
    __shared__ float h[HID];
    int t = threadIdx.x;  // 192 threads
    if (t < FDIM)            comb[t] = g_atom_sum[t] / n_atoms_f;
    else if (t < 2 * FDIM)   comb[t] = g_bond_sum[t - FDIM] / n_bonds_f;
    else if (t < 3 * FDIM)   comb[t] = gfeat[t - 2 * FDIM];
    __syncthreads();
    if (t < HID) {
        float a = bg1[t];
#pragma unroll 4
        for (int k = 0; k < 3 * FDIM; k++) a += comb[k] * Wg1[(size_t)k * HID + t];
        h[t] = softplus_f(a);
    }
    __syncthreads();
    if (t < FDIM) {
        float a = bg2[t] + gfeat[t];
#pragma unroll 4
        for (int k = 0; k < HID; k++) a += h[k] * Wg2[(size_t)k * FDIM + t];
        outg[t] = a;
    }
}

// ---------------- launch ----------------
extern "C" void kernel_launch(void* const* d_in, const int* in_sizes, int n_in,
                              void* d_out, int out_size)
{
    const float* atom_f = (const float*)d_in[0];
    const float* bond_f = (const float*)d_in[1];
    const float* gfeat  = (const float*)d_in[2];
    const float* Wb1 = (const float*)d_in[3];
    const float* bb1 = (const float*)d_in[4];
    const float* Wb2 = (const float*)d_in[5];
    const float* bb2 = (const float*)d_in[6];
    const float* Wa1 = (const float*)d_in[7];
    const float* ba1 = (const float*)d_in[8];
    const float* Wa2 = (const float*)d_in[9];
    const float* ba2 = (const float*)d_in[10];
    const float* Wg1 = (const float*)d_in[11];
    const float* bg1 = (const float*)d_in[12];
    const float* Wg2 = (const float*)d_in[13];
    const float* bg2 = (const float*)d_in[14];
    const int* ab_idx = (const int*)d_in[15];
    const int* ba_idx = (const int*)d_in[16];

    const int n_atoms = in_sizes[0] / FDIM;
    const int n_bonds = in_sizes[1] / FDIM;
    const int max_deg = in_sizes[16] / n_atoms;

    float* out       = (float*)d_out;
    float* out_atoms = out;
    float* out_bonds = out + (size_t)n_atoms * FDIM;
    float* out_glob  = out + (size_t)n_atoms * FDIM + (size_t)n_bonds * FDIM;

    cudaFuncSetAttribute(mlp_tc<0>, cudaFuncAttributeMaxDynamicSharedMemorySize, SMEM_SZ);
    cudaFuncSetAttribute(mlp_tc<1>, cudaFuncAttributeMaxDynamicSharedMemorySize, SMEM_SZ);

    unsigned short *pwb1, *pwb2, *pwa1, *pwa2;
    cudaGetSymbolAddress((void**)&pwb1, wb1_img);
    cudaGetSymbolAddress((void**)&pwb2, wb2_img);
    cudaGetSymbolAddress((void**)&pwa1, wa1_img);
    cudaGetSymbolAddress((void**)&pwa2, wa2_img);

    int nsm = 148;
    cudaDeviceGetAttribute(&nsm, cudaDevAttrMultiProcessorCount, 0);

    init_kernel<<<1, 128>>>();

    const int prep_elems = HID * 4 * FDIM + FDIM * HID;
    prep_weights<<<(prep_elems + 255) / 256, 256>>>(Wb1, Wb2, pwb1, pwb2);
    prep_weights<<<(prep_elems + 255) / 256, 256>>>(Wa1, Wa2, pwa1, pwa2);

    const int n4 = n_atoms * (FDIM / 4);
    prep_atom<<<(n4 + 255) / 256, 256>>>(atom_f, gfeat, n4);

    const int bond_tiles = (n_bonds + 127) / 128;
    int grid0 = nsm < bond_tiles ? nsm : bond_tiles;
    mlp_tc<0><<<grid0, 512, SMEM_SZ>>>(
        nullptr, bond_f, bb1, bb2, ab_idx, pwb1, pwb2, out_bonds, n_bonds);

    const int agg_blocks = ((n_atoms * 32) + 255) / 256;
    agg_kernel<<<agg_blocks, 256>>>(ba_idx, n_atoms, max_deg);

    const int atom_tiles = (n_atoms + 127) / 128;
    int grid1 = nsm < atom_tiles ? nsm : atom_tiles;
    mlp_tc<1><<<grid1, 512, SMEM_SZ>>>(
        atom_f, nullptr, ba1, ba2, nullptr, pwa1, pwa2, out_atoms, n_atoms);

    global_kernel<<<1, 192>>>(gfeat, Wg1, bg1, Wg2, bg2, out_glob,
                              (float)n_atoms, (float)n_bonds);
}

// round 10
// speedup vs baseline: 3.1625x; 1.0513x over previous
#include <cuda_runtime.h>
#include <cuda_fp16.h>
#include <math.h>
#include <stdint.h>

#define FDIM 64
#define HID  128
#define N_ATOMS_MAX 100000
#define N_BONDS_MAX 800000

// ---------------- device scratch (no allocs allowed) ----------------
__device__ float g_bond_sum[FDIM];
__device__ float g_atom_sum[FDIM];
__device__ __align__(16) unsigned short g_atom_h[(size_t)N_ATOMS_MAX * FDIM]; // fp16 atom feats
__device__ __align__(16) unsigned short g_agg_h [(size_t)N_ATOMS_MAX * FDIM]; // fp16 agg
__device__ __align__(16) unsigned short g_bond_h[(size_t)N_BONDS_MAX * FDIM]; // fp16 updated bonds
__device__ __align__(16) unsigned short g_h_dev[FDIM];                        // fp16 global feats
// pre-transposed fp16 weight images: W^T stored [N][K] row-major
__device__ __align__(16) unsigned short wb1_img[HID * 4 * FDIM];   // [128][256]
__device__ __align__(16) unsigned short wb2_img[FDIM * HID];       // [64][128]
__device__ __align__(16) unsigned short wa1_img[HID * 4 * FDIM];
__device__ __align__(16) unsigned short wa2_img[FDIM * HID];

// ---------------- helpers ----------------
__device__ __forceinline__ float softplus_f(float x) {
    float t = __expf(-fabsf(x));
    return fmaxf(x, 0.f) + __logf(1.f + t);
}
__device__ __forceinline__ uint32_t pack_h2(float a, float b) {
    __half2 h = __floats2half2_rn(a, b);
    return *(uint32_t*)&h;
}
__device__ __forceinline__ uint32_t smem_u32(const void* p) {
    uint32_t a;
    asm("{ .reg .u64 t; cvta.to.shared.u64 t, %1; cvt.u32.u64 %0, t; }"
        : "=r"(a) : "l"(p));
    return a;
}
__device__ __forceinline__ void ldm_x4(uint32_t (&r)[4], uint32_t addr) {
    asm volatile("ldmatrix.sync.aligned.m8n8.x4.shared.b16 {%0,%1,%2,%3}, [%4];"
                 : "=r"(r[0]), "=r"(r[1]), "=r"(r[2]), "=r"(r[3]) : "r"(addr));
}
__device__ __forceinline__ void mma16816(float (&d)[4], const uint32_t (&a)[4],
                                         uint32_t b0, uint32_t b1) {
    asm volatile("mma.sync.aligned.m16n8k16.row.col.f32.f16.f16.f32 "
                 "{%0,%1,%2,%3}, {%4,%5,%6,%7}, {%8,%9}, {%0,%1,%2,%3};"
                 : "+f"(d[0]), "+f"(d[1]), "+f"(d[2]), "+f"(d[3])
                 : "r"(a[0]), "r"(a[1]), "r"(a[2]), "r"(a[3]), "r"(b0), "r"(b1));
}
__device__ __forceinline__ void cpa16(uint32_t dst, const void* src) {
    asm volatile("cp.async.ca.shared.global [%0], [%1], 16;"
                 :: "r"(dst), "l"(src));
}
__device__ __forceinline__ void cpa_wait_all() {
    asm volatile("cp.async.wait_all;" ::: "memory");
}

// ---------------- init ----------------
__global__ void init_kernel() {
    int t = threadIdx.x;
    if (t < FDIM) { g_bond_sum[t] = 0.f; g_atom_sum[t] = 0.f; }
}

// ---------------- weight transpose + fp16 convert ----------------
__global__ void prep_weights(const float* __restrict__ W1, const float* __restrict__ W2,
                             unsigned short* __restrict__ img1,
                             unsigned short* __restrict__ img2) {
    int idx = blockIdx.x * blockDim.x + threadIdx.x;
    if (idx < HID * 4 * FDIM) {                 // W1^T [128][256]
        int n = idx >> 8, k = idx & 255;
        __half h = __float2half_rn(W1[(size_t)k * HID + n]);
        img1[idx] = *(unsigned short*)&h;
    } else if (idx < HID * 4 * FDIM + FDIM * HID) {  // W2^T [64][128]
        int t = idx - HID * 4 * FDIM;
        int n = t >> 7, k = t & 127;
        __half h = __float2half_rn(W2[(size_t)k * FDIM + n]);
        img2[t] = *(unsigned short*)&h;
    }
}

// ---------------- atom features + gfeat -> fp16 ----------------
__global__ void prep_atom(const float* __restrict__ atom_f,
                          const float* __restrict__ gfeat, int n4) {
    int idx = blockIdx.x * blockDim.x + threadIdx.x;
    if (idx < n4) {
        float4 v = ((const float4*)atom_f)[idx];
        uint2 o = make_uint2(pack_h2(v.x, v.y), pack_h2(v.z, v.w));
        ((uint2*)g_atom_h)[idx] = o;
    }
    if (blockIdx.x == 0 && threadIdx.x < 16) {
        float4 v = ((const float4*)gfeat)[threadIdx.x];
        ((uint2*)g_h_dev)[threadIdx.x] = make_uint2(pack_h2(v.x, v.y), pack_h2(v.z, v.w));
    }
}

// ---------------- SMEM layout (bytes) ----------------
static constexpr int ASTRIDE = 528;   // 256+8 halves
static constexpr int HSTRIDE = 272;   // 128+8 halves
static constexpr int SM_A  = 0;                          // 128 rows (4 groups x 32)
static constexpr int SM_W1 = SM_A + 128 * ASTRIDE;       // 67584
static constexpr int SM_H  = SM_W1 + 128 * ASTRIDE;      // 135168
static constexpr int SM_W2 = SM_H + 128 * HSTRIDE;       // 169984
static constexpr int SM_B1 = SM_W2 + 64 * HSTRIDE;       // 187392
static constexpr int SM_B2 = SM_B1 + 512;                // 187904
static constexpr int SM_CS = SM_B2 + 256;                // 188160
static constexpr int SM_RES = SM_CS + 256;               // 188416 (128 rows x 256B fp32)
static constexpr int SMEM_SZ = SM_RES + 128 * 256;       // 221184

// ---------------- persistent fused 2-layer MLP (mma.sync) ----------------
// 4 independent 128-thread groups per CTA; each owns a 32-row tile stream.
// MODE 0 (bonds): comb = [atom_h[i], atom_h[j], f16(bond_f[row]), g_h]
// MODE 1 (atoms): comb = [atom_h[row], agg_h[row], atom_h[row], g_h]
template <int MODE>
__global__ __launch_bounds__(512, 1)
void mlp_tc(const float* __restrict__ resid_glob,   // MODE1: atom_f
            const float* __restrict__ bond_f,       // MODE0 only
            const float* __restrict__ b1, const float* __restrict__ b2,
            const int*   __restrict__ ab_idx,       // MODE0 only
            const unsigned short* __restrict__ w1img,
            const unsigned short* __restrict__ w2img,
            float* __restrict__ outp,
            int n_rows)
{
    extern __shared__ __align__(16) char smem[];
    const uint32_t sb = smem_u32(smem);
    float* bias1  = (float*)(smem + SM_B1);
    float* bias2  = (float*)(smem + SM_B2);
    float* colsum = (float*)(smem + SM_CS);

    const int tid = threadIdx.x, wid = tid >> 5, lane = tid & 31;
    const int gid = wid >> 2;            // group 0..3
    const int warp_n = wid & 3;          // n-column split within group
    const int tg = tid & 127;            // thread-in-group
    const int n_tiles = (n_rows + 31) >> 5;   // 32-row tiles

    // ---- one-time staging: weights (padded stride), biases, colsum ----
    for (int i = tid; i < 4096; i += 512) {               // W1T: 128 rows x 32 uint4
        int r = i >> 5, c = i & 31;
        *(uint4*)(smem + SM_W1 + r * ASTRIDE + c * 16) = ((const uint4*)w1img)[i];
    }
    for (int i = tid; i < 1024; i += 512) {               // W2T: 64 rows x 16 uint4
        int r = i >> 4, c = i & 15;
        *(uint4*)(smem + SM_W2 + r * HSTRIDE + c * 16) = ((const uint4*)w2img)[i];
    }
    if (tid < HID)  bias1[tid] = b1[tid];
    if (tid < FDIM) { bias2[tid] = b2[tid]; colsum[tid] = 0.f; }

    // gather thread mapping: 4 threads per row, 32 rows per group
    const int grow_r = tg >> 2, qs = tg & 3;

    // ldmatrix lane-address components
    const uint32_t aLane1 = (uint32_t)((lane & 15) * ASTRIDE + (lane >> 4) * 16);
    const uint32_t aLane2 = (uint32_t)((lane & 15) * HSTRIDE + (lane >> 4) * 16);
    const uint32_t bN = (uint32_t)((lane & 7) + ((lane >> 4) << 3));
    const uint32_t bK = (uint32_t)(((lane >> 3) & 1) * 16);
    const uint32_t aBase1 = sb + SM_A + (uint32_t)(gid * 32) * ASTRIDE + aLane1;
    const uint32_t bBase1 = sb + SM_W1 + (uint32_t)(warp_n * 32 + bN) * ASTRIDE + bK;
    const uint32_t aBase2 = sb + SM_H + (uint32_t)(gid * 32) * HSTRIDE + aLane2;
    const uint32_t bBase2 = sb + SM_W2 + (uint32_t)(warp_n * 16 + bN) * HSTRIDE + bK;

    float ls[2][2] = {{0.f, 0.f}, {0.f, 0.f}};   // per-thread running column sums

    // async gather of fp16 A segments for one 32-row tile (group-local)
    auto gather_async = [&](int t) {
        int gr = t * 32 + grow_r;
        int grc = gr < n_rows ? gr : n_rows - 1;
        const uint32_t dstrow = sb + SM_A + (uint32_t)(gid * 32 + grow_r) * ASTRIDE;
        if (MODE == 0) {
            if (qs == 0) {
                const char* src = (const char*)(g_atom_h + (size_t)ab_idx[2 * grc] * FDIM);
#pragma unroll
                for (int q = 0; q < 8; q++) cpa16(dstrow + q * 16, src + q * 16);
            } else if (qs == 1) {
                const char* src = (const char*)(g_atom_h + (size_t)ab_idx[2 * grc + 1] * FDIM);
#pragma unroll
                for (int q = 0; q < 8; q++) cpa16(dstrow + 128 + q * 16, src + q * 16);
            } else if (qs == 2) {
#pragma unroll
                for (int q = 0; q < 4; q++) cpa16(dstrow + 384 + q * 16, (const char*)g_h_dev + q * 16);
            } else {
#pragma unroll
                for (int q = 0; q < 4; q++) cpa16(dstrow + 448 + q * 16, (const char*)g_h_dev + 64 + q * 16);
            }
        } else {
            const char* arow = (const char*)(g_atom_h + (size_t)grc * FDIM);
            if (qs == 0) {
#pragma unroll
                for (int q = 0; q < 8; q++) cpa16(dstrow + q * 16, arow + q * 16);
            } else if (qs == 1) {
                const char* src = (const char*)(g_agg_h + (size_t)grc * FDIM);
#pragma unroll
                for (int q = 0; q < 8; q++) cpa16(dstrow + 128 + q * 16, src + q * 16);
            } else if (qs == 2) {
#pragma unroll
                for (int q = 0; q < 8; q++) cpa16(dstrow + 256 + q * 16, arow + q * 16);
            } else {
#pragma unroll
                for (int q = 0; q < 8; q++) cpa16(dstrow + 384 + q * 16, (const char*)g_h_dev + q * 16);
            }
        }
    };

    // prefetch of the bond fp32 row quarter (residual + A seg2 source) in regs
    float4 pb0, pb1, pb2, pb3;
    auto load_bond = [&](int t) {
        if (MODE == 0) {
            int gr = t * 32 + grow_r;
            int grc = gr < n_rows ? gr : n_rows - 1;
            const float4* bs = (const float4*)(bond_f + (size_t)grc * FDIM) + qs * 4;
            pb0 = bs[0]; pb1 = bs[1]; pb2 = bs[2]; pb3 = bs[3];
        }
    };

    const int stride = (int)gridDim.x * 4;
    int tile = blockIdx.x * 4 + gid;
    if (tile < n_tiles) { gather_async(tile); load_bond(tile); }
    __syncthreads();                       // weights/bias staged (CTA-wide, once)

    for (; tile < n_tiles; tile += stride) {
        const int row_base = tile * 32;

        // ---- commit prefetched bond row: fp16 -> A seg2, fp32 -> RES ----
        if (MODE == 0) {
            char* adst = smem + SM_A + (gid * 32 + grow_r) * ASTRIDE + 256 + qs * 32;
            ((uint4*)adst)[0] = make_uint4(pack_h2(pb0.x, pb0.y), pack_h2(pb0.z, pb0.w),
                                           pack_h2(pb1.x, pb1.y), pack_h2(pb1.z, pb1.w));
            ((uint4*)adst)[1] = make_uint4(pack_h2(pb2.x, pb2.y), pack_h2(pb2.z, pb2.w),
                                           pack_h2(pb3.x, pb3.y), pack_h2(pb3.z, pb3.w));
            float4* rdst = (float4*)(smem + SM_RES + (gid * 32 + grow_r) * 256) + qs * 4;
            rdst[0] = pb0; rdst[1] = pb1; rdst[2] = pb2; rdst[3] = pb3;
        }
        cpa_wait_all();
        asm volatile("bar.sync %0, 128;" :: "r"(gid + 1) : "memory");   // A/RES ready

        // ---- layer 1: c1 (32 rows x 32 cols per warp) ----
        float c1[2][4][4];
#pragma unroll
        for (int mi = 0; mi < 2; mi++)
#pragma unroll
            for (int nb = 0; nb < 4; nb++)
#pragma unroll
                for (int j = 0; j < 4; j++) c1[mi][nb][j] = 0.f;

#pragma unroll
        for (int k0 = 0; k0 < 256; k0 += 16) {
            uint32_t a0[4], a1[4];
            ldm_x4(a0, aBase1 + k0 * 2);
            ldm_x4(a1, aBase1 + 16 * ASTRIDE + k0 * 2);
#pragma unroll
            for (int g = 0; g < 2; g++) {
                uint32_t bf[4];
                ldm_x4(bf, bBase1 + (uint32_t)(g * 16) * ASTRIDE + k0 * 2);
                mma16816(c1[0][2 * g],     a0, bf[0], bf[1]);
                mma16816(c1[0][2 * g + 1], a0, bf[2], bf[3]);
                mma16816(c1[1][2 * g],     a1, bf[0], bf[1]);
                mma16816(c1[1][2 * g + 1], a1, bf[2], bf[3]);
            }
        }

        // ---- epilogue 1: bias + softplus -> fp16 H (group slice) ----
        {
            const int r0 = lane >> 2;
            const int cb = warp_n * 32 + (lane & 3) * 2;
#pragma unroll
            for (int mi = 0; mi < 2; mi++) {
#pragma unroll
                for (int nb = 0; nb < 4; nb++) {
                    int col = cb + nb * 8;
                    float b0v = bias1[col], b1v = bias1[col + 1];
                    uint32_t p0 = pack_h2(softplus_f(c1[mi][nb][0] + b0v),
                                          softplus_f(c1[mi][nb][1] + b1v));
                    uint32_t p1 = pack_h2(softplus_f(c1[mi][nb][2] + b0v),
                                          softplus_f(c1[mi][nb][3] + b1v));
                    int row = gid * 32 + mi * 16 + r0;
                    *(uint32_t*)(smem + SM_H + row * HSTRIDE + col * 2) = p0;
                    *(uint32_t*)(smem + SM_H + (row + 8) * HSTRIDE + col * 2) = p1;
                }
            }
        }
        asm volatile("bar.sync %0, 128;" :: "r"(gid + 1) : "memory");   // H ready, A free

        // ---- prefetch next tile (overlaps MMA2 + epilogue2) ----
        if (tile + stride < n_tiles) { gather_async(tile + stride); load_bond(tile + stride); }

        // ---- layer 2: c2 (32 rows x 16 cols per warp) ----
        float c2[2][2][4];
#pragma unroll
        for (int mi = 0; mi < 2; mi++)
#pragma unroll
            for (int nb = 0; nb < 2; nb++)
#pragma unroll
                for (int j = 0; j < 4; j++) c2[mi][nb][j] = 0.f;

#pragma unroll
        for (int k0 = 0; k0 < 128; k0 += 16) {
            uint32_t a0[4], a1[4], bf[4];
            ldm_x4(a0, aBase2 + k0 * 2);
            ldm_x4(a1, aBase2 + 16 * HSTRIDE + k0 * 2);
            ldm_x4(bf, bBase2 + k0 * 2);
            mma16816(c2[0][0], a0, bf[0], bf[1]);
            mma16816(c2[0][1], a0, bf[2], bf[3]);
            mma16816(c2[1][0], a1, bf[0], bf[1]);
            mma16816(c2[1][1], a1, bf[2], bf[3]);
        }

        // ---- epilogue 2: bias + residual + stores + running column sums ----
        {
            const int cb2 = warp_n * 16 + (lane & 3) * 2;
#pragma unroll
            for (int mi = 0; mi < 2; mi++) {
#pragma unroll
                for (int half = 0; half < 2; half++) {
                    int row = mi * 16 + half * 8 + (lane >> 2);
                    int grow = row_base + row;
                    if (grow < n_rows) {
#pragma unroll
                        for (int nb = 0; nb < 2; nb++) {
                            int col = cb2 + nb * 8;
                            float v0 = c2[mi][nb][half * 2 + 0] + bias2[col];
                            float v1 = c2[mi][nb][half * 2 + 1] + bias2[col + 1];
                            float2 rv;
                            if (MODE == 0)
                                rv = *(const float2*)(smem + SM_RES + (gid * 32 + row) * 256 + col * 4);
                            else
                                rv = *(const float2*)&resid_glob[(size_t)grow * FDIM + col];
                            float2 o = make_float2(v0 + rv.x, v1 + rv.y);
                            *(float2*)&outp[(size_t)grow * FDIM + col] = o;
                            if (MODE == 0)
                                ((uint32_t*)g_bond_h)[(size_t)grow * 32 + (col >> 1)] =
                                    pack_h2(o.x, o.y);
                            ls[nb][0] += o.x; ls[nb][1] += o.y;
                        }
                    }
                }
            }
        }
        asm volatile("bar.sync %0, 128;" :: "r"(gid + 1) : "memory");   // RES/A reusable
    }

    // ---- flush column sums ----
#pragma unroll
    for (int nb = 0; nb < 2; nb++) {
        int col = warp_n * 16 + (lane & 3) * 2 + nb * 8;
        atomicAdd(&colsum[col],     ls[nb][0]);
        atomicAdd(&colsum[col + 1], ls[nb][1]);
    }
    __syncthreads();
    if (tid < FDIM) {
        float* gsum = (MODE == 0) ? g_bond_sum : g_atom_sum;
        atomicAdd(&gsum[tid], colsum[tid]);
    }
}

// ---------------- bond -> atom masked mean aggregation (fp16 in/out) -------
__global__ void agg_kernel(const int* __restrict__ bai, int n_atoms, int max_deg)
{
    int warp = (blockIdx.x * blockDim.x + threadIdx.x) >> 5;
    int lane = threadIdx.x & 31;
    if (warp >= n_atoms) return;
    int myidx = (lane < max_deg) ? bai[(size_t)warp * max_deg + lane] : -1;
    unsigned mb = __ballot_sync(0xffffffffu, myidx >= 0);
    int cnt = __popc(mb);
    float sx = 0.f, sy = 0.f;
#pragma unroll
    for (int d = 0; d < 32; d += 8) {
        if (d >= max_deg) break;
        int i0 = __shfl_sync(0xffffffffu, myidx, d + 0);
        int i1 = __shfl_sync(0xffffffffu, myidx, d + 1);
        int i2 = __shfl_sync(0xffffffffu, myidx, d + 2);
        int i3 = __shfl_sync(0xffffffffu, myidx, d + 3);
        int i4 = __shfl_sync(0xffffffffu, myidx, d + 4);
        int i5 = __shfl_sync(0xffffffffu, myidx, d + 5);
        int i6 = __shfl_sync(0xffffffffu, myidx, d + 6);
        int i7 = __shfl_sync(0xffffffffu, myidx, d + 7);
        int ids[8] = {i0, i1, i2, i3, i4, i5, i6, i7};
#pragma unroll
        for (int q = 0; q < 8; q++) {
            if (d + q < max_deg && ids[q] >= 0) {
                uint32_t u = ((const uint32_t*)g_bond_h)[(size_t)ids[q] * 32 + lane];
                float2 v = __half22float2(*(__half2*)&u);
                sx += v.x; sy += v.y;
            }
        }
    }
    float inv = 1.f / fmaxf((float)cnt, 1.f);
    ((uint32_t*)g_agg_h)[(size_t)warp * 32 + lane] = pack_h2(sx * inv, sy * inv);
}

// ---------------- global MLP ----------------
__global__ void global_kernel(const float* __restrict__ gfeat,
                              const float* __restrict__ Wg1, const float* __restrict__ bg1,
                              const float* __restrict__ Wg2, const float* __restrict__ bg2,
                              float* __restrict__ outg,
                              float n_atoms_f, float n_bonds_f)
{
    __shared__ float comb[3 * FDIM];
    __shared__ float h[HID];
    int t = threadIdx.x;  // 192 threads
    if (t < FDIM)            comb[t] = g_atom_sum[t] / n_atoms_f;
    else if (t < 2 * FDIM)   comb[t] = g_bond_sum[t - FDIM] / n_bonds_f;
    else if (t < 3 * FDIM)   comb[t] = gfeat[t - 2 * FDIM];
    __syncthreads();
    if (t < HID) {
        float a = bg1[t];
#pragma unroll 4
        for (int k = 0; k < 3 * FDIM; k++) a += comb[k] * Wg1[(size_t)k * HID + t];
        h[t] = softplus_f(a);
    }
    __syncthreads();
    if (t < FDIM) {
        float a = bg2[t] + gfeat[t];
#pragma unroll 4
        for (int k = 0; k < HID; k++) a += h[k] * Wg2[(size_t)k * FDIM + t];
        outg[t] = a;
    }
}

// ---------------- launch ----------------
extern "C" void kernel_launch(void* const* d_in, const int* in_sizes, int n_in,
                              void* d_out, int out_size)
{
    const float* atom_f = (const float*)d_in[0];
    const float* bond_f = (const float*)d_in[1];
    const float* gfeat  = (const float*)d_in[2];
    const float* Wb1 = (const float*)d_in[3];
    const float* bb1 = (const float*)d_in[4];
    const float* Wb2 = (const float*)d_in[5];
    const float* bb2 = (const float*)d_in[6];
    const float* Wa1 = (const float*)d_in[7];
    const float* ba1 = (const float*)d_in[8];
    const float* Wa2 = (const float*)d_in[9];
    const float* ba2 = (const float*)d_in[10];
    const float* Wg1 = (const float*)d_in[11];
    const float* bg1 = (const float*)d_in[12];
    const float* Wg2 = (const float*)d_in[13];
    const float* bg2 = (const float*)d_in[14];
    const int* ab_idx = (const int*)d_in[15];
    const int* ba_idx = (const int*)d_in[16];

    const int n_atoms = in_sizes[0] / FDIM;
    const int n_bonds = in_sizes[1] / FDIM;
    const int max_deg = in_sizes[16] / n_atoms;

    float* out       = (float*)d_out;
    float* out_atoms = out;
    float* out_bonds = out + (size_t)n_atoms * FDIM;
    float* out_glob  = out + (size_t)n_atoms * FDIM + (size_t)n_bonds * FDIM;

    cudaFuncSetAttribute(mlp_tc<0>, cudaFuncAttributeMaxDynamicSharedMemorySize, SMEM_SZ);
    cudaFuncSetAttribute(mlp_tc<1>, cudaFuncAttributeMaxDynamicSharedMemorySize, SMEM_SZ);

    unsigned short *pwb1, *pwb2, *pwa1, *pwa2;
    cudaGetSymbolAddress((void**)&pwb1, wb1_img);
    cudaGetSymbolAddress((void**)&pwb2, wb2_img);
    cudaGetSymbolAddress((void**)&pwa1, wa1_img);
    cudaGetSymbolAddress((void**)&pwa2, wa2_img);

    int nsm = 148;
    cudaDeviceGetAttribute(&nsm, cudaDevAttrMultiProcessorCount, 0);

    init_kernel<<<1, 128>>>();

    const int prep_elems = HID * 4 * FDIM + FDIM * HID;
    prep_weights<<<(prep_elems + 255) / 256, 256>>>(Wb1, Wb2, pwb1, pwb2);
    prep_weights<<<(prep_elems + 255) / 256, 256>>>(Wa1, Wa2, pwa1, pwa2);

    const int n4 = n_atoms * (FDIM / 4);
    prep_atom<<<(n4 + 255) / 256, 256>>>(atom_f, gfeat, n4);

    const int bond_tiles32 = (n_bonds + 31) / 32;
    int grid0 = nsm < (bond_tiles32 + 3) / 4 ? nsm : (bond_tiles32 + 3) / 4;
    if (grid0 < 1) grid0 = 1;
    mlp_tc<0><<<grid0, 512, SMEM_SZ>>>(
        nullptr, bond_f, bb1, bb2, ab_idx, pwb1, pwb2, out_bonds, n_bonds);

    const int agg_blocks = ((n_atoms * 32) + 255) / 256;
    agg_kernel<<<agg_blocks, 256>>>(ba_idx, n_atoms, max_deg);

    const int atom_tiles32 = (n_atoms + 31) / 32;
    int grid1 = nsm < (atom_tiles32 + 3) / 4 ? nsm : (atom_tiles32 + 3) / 4;
    if (grid1 < 1) grid1 = 1;
    mlp_tc<1><<<grid1, 512, SMEM_SZ>>>(
        atom_f, nullptr, ba1, ba2, nullptr, pwa1, pwa2, out_atoms, n_atoms);

    global_kernel<<<1, 192>>>(gfeat, Wg1, bg1, Wg2, bg2, out_glob,
                              (float)n_atoms, (float)n_bonds);
}